// round 14
// baseline (speedup 1.0000x reference)
#include <cuda_runtime.h>
#include <cuda_bf16.h>
#include <stdint.h>

// GCN 2-layer, atomic-scatter formulation:
//   g   = (x @ W) * dinv[row]           (dinv = rsqrt(indeg+1))
//   acc[d] = g[d] + sum_{e:dst=d} g[src_e]      (red.global.add.v4)
//   y   = dinv[d] * acc[d] + b

#define NMAX 100096
#define F_IN 128
#define H1 32
#define H2 16

__device__ float g_cnt[NMAX];         // edge in-degree (float), +1 folded later
__device__ float g_dinv[NMAX];
__device__ float g_g1[NMAX * H1];
__device__ float g_acc1[NMAX * H1];
__device__ float g_g2[NMAX * H2];

// ---------------------------------------------------------------- degree ----
__global__ void k_zero_deg(int n) {
    int i = blockIdx.x * blockDim.x + threadIdx.x;
    if (i < n) g_cnt[i] = 0.0f;
}

__global__ void k_count_deg(const int* __restrict__ dst, int E) {
    int e = blockIdx.x * blockDim.x + threadIdx.x;
    if (e < E) atomicAdd(&g_cnt[dst[e]], 1.0f);  // no-return -> RED
}

// ------------------------------------------------------------- layer 1 ------
// Block = 64 rows. x tile staged in smem with fully-coalesced cooperative
// loads; bank conflicts avoided via XOR swizzle on float4 units (no padding,
// so Ws+xs = exactly 48 KB static smem). W1 held in registers per k4 chunk.
// Thread = 2 rows x 4 cols. Also computes dinv (self-loop +1 folded) and
// initializes acc1 = g1.
#define XS_SWZ(r, u) (((r) << 5) | ((u) ^ ((r) & 31)))   // float4-unit index

__global__ void __launch_bounds__(256) k_gemm1(const float* __restrict__ x,
                                               const float* __restrict__ W1, int n) {
    __shared__ float  Ws[F_IN * H1];      // 16 KB
    __shared__ float4 xs4[64 * 32];       // 32 KB (64 rows x 32 float4 units)
    int tid = threadIdx.x;
    int row0 = blockIdx.x * 64;

    for (int i = tid; i < F_IN * H1; i += 256) Ws[i] = W1[i];

    // coalesced x tile load: 64 rows x 32 float4, swizzled store
    const float4* xg = (const float4*)(x + (size_t)row0 * F_IN);
    int nrow = min(64, n - row0);
    for (int i = tid; i < 64 * 32; i += 256) {
        int r = i >> 5, u = i & 31;
        if (r < nrow) xs4[XS_SWZ(r, u)] = xg[i];
    }
    __syncthreads();

    int lane = tid & 31, warp = tid >> 5;
    int c0 = (lane & 7) * 4;     // colgroup -> 4 output cols
    int rg = lane >> 3;          // rowgroup (0..3)
    int r0 = warp * 8 + rg * 2;  // local row; thread does r0, r0+1

    float acc[2][4] = {};
#pragma unroll
    for (int k4 = 0; k4 < F_IN; k4 += 4) {
        int u = k4 >> 2;
        float4 xa = xs4[XS_SWZ(r0, u)];
        float4 xb = xs4[XS_SWZ(r0 + 1, u)];
        float4 w0 = *(const float4*)&Ws[(k4 + 0) * H1 + c0];
        float4 w1 = *(const float4*)&Ws[(k4 + 1) * H1 + c0];
        float4 w2 = *(const float4*)&Ws[(k4 + 2) * H1 + c0];
        float4 w3 = *(const float4*)&Ws[(k4 + 3) * H1 + c0];

        acc[0][0] = fmaf(xa.x, w0.x, acc[0][0]);
        acc[0][1] = fmaf(xa.x, w0.y, acc[0][1]);
        acc[0][2] = fmaf(xa.x, w0.z, acc[0][2]);
        acc[0][3] = fmaf(xa.x, w0.w, acc[0][3]);
        acc[0][0] = fmaf(xa.y, w1.x, acc[0][0]);
        acc[0][1] = fmaf(xa.y, w1.y, acc[0][1]);
        acc[0][2] = fmaf(xa.y, w1.z, acc[0][2]);
        acc[0][3] = fmaf(xa.y, w1.w, acc[0][3]);
        acc[0][0] = fmaf(xa.z, w2.x, acc[0][0]);
        acc[0][1] = fmaf(xa.z, w2.y, acc[0][1]);
        acc[0][2] = fmaf(xa.z, w2.z, acc[0][2]);
        acc[0][3] = fmaf(xa.z, w2.w, acc[0][3]);
        acc[0][0] = fmaf(xa.w, w3.x, acc[0][0]);
        acc[0][1] = fmaf(xa.w, w3.y, acc[0][1]);
        acc[0][2] = fmaf(xa.w, w3.z, acc[0][2]);
        acc[0][3] = fmaf(xa.w, w3.w, acc[0][3]);

        acc[1][0] = fmaf(xb.x, w0.x, acc[1][0]);
        acc[1][1] = fmaf(xb.x, w0.y, acc[1][1]);
        acc[1][2] = fmaf(xb.x, w0.z, acc[1][2]);
        acc[1][3] = fmaf(xb.x, w0.w, acc[1][3]);
        acc[1][0] = fmaf(xb.y, w1.x, acc[1][0]);
        acc[1][1] = fmaf(xb.y, w1.y, acc[1][1]);
        acc[1][2] = fmaf(xb.y, w1.z, acc[1][2]);
        acc[1][3] = fmaf(xb.y, w1.w, acc[1][3]);
        acc[1][0] = fmaf(xb.z, w2.x, acc[1][0]);
        acc[1][1] = fmaf(xb.z, w2.y, acc[1][1]);
        acc[1][2] = fmaf(xb.z, w2.z, acc[1][2]);
        acc[1][3] = fmaf(xb.z, w2.w, acc[1][3]);
        acc[1][0] = fmaf(xb.w, w3.x, acc[1][0]);
        acc[1][1] = fmaf(xb.w, w3.y, acc[1][1]);
        acc[1][2] = fmaf(xb.w, w3.z, acc[1][2]);
        acc[1][3] = fmaf(xb.w, w3.w, acc[1][3]);
    }

#pragma unroll
    for (int r = 0; r < 2; r++) {
        int row = row0 + r0 + r;
        if (row < n) {
            float di = rsqrtf(g_cnt[row] + 1.0f);   // +1 = self loop
            if (c0 == 0) g_dinv[row] = di;  // one writer per row (colgroup 0)
            float4 v = make_float4(acc[r][0] * di, acc[r][1] * di,
                                   acc[r][2] * di, acc[r][3] * di);
            *(float4*)&g_g1[row * H1 + c0]   = v;
            *(float4*)&g_acc1[row * H1 + c0] = v;
        }
    }
}

// per-edge scatter: acc1[dst] += g1[src]  (32 floats = 8 x red.v4)
__global__ void k_scatter1(const int* __restrict__ src, const int* __restrict__ dst, int E) {
    long long tid = (long long)blockIdx.x * blockDim.x + threadIdx.x;
    if (tid >= (long long)E * 8) return;
    int e = (int)(tid >> 3), c = (int)(tid & 7);
    int s = __ldg(&src[e]);
    int d = __ldg(&dst[e]);
    float4 v = ((const float4*)(g_g1 + s * H1))[c];
    float* p = g_acc1 + d * H1 + c * 4;
    asm volatile("red.global.add.v4.f32 [%0], {%1,%2,%3,%4};"
                 :: "l"(p), "f"(v.x), "f"(v.y), "f"(v.z), "f"(v.w) : "memory");
}

// epilogue layer1 + GEMM2 fused (warp shuffles), writes g2 and out self-loop.
__global__ void k_finish1_gemm2(const float* __restrict__ W2, const float* __restrict__ b1,
                                float* __restrict__ out, int n) {
    __shared__ float W2s[H1 * H2];  // 2 KB
    __shared__ float b1s[H1];
    int tid = threadIdx.x;  // 256
    for (int i = tid; i < H1 * H2; i += 256) W2s[i] = W2[i];
    if (tid < H1) b1s[tid] = b1[tid];
    __syncthreads();

    int warp = tid >> 5, lane = tid & 31;
    int row = blockIdx.x * 8 + warp;
    if (row >= n) return;

    float di = g_dinv[row];
    float h = fmaxf(fmaf(di, g_acc1[row * H1 + lane], b1s[lane]), 0.0f);

    float acc = 0.0f;
    int j = lane & 15;
#pragma unroll
    for (int k = 0; k < H1; k++) {
        float v = __shfl_sync(0xffffffffu, h, k);
        acc = fmaf(v, W2s[k * H2 + j], acc);
    }
    if (lane < H2) {
        float g = acc * di;
        g_g2[row * H2 + lane] = g;
        out[row * H2 + lane]  = g;
    }
}

// per-edge scatter layer 2: out[dst] += g2[src]  (16 floats = 4 x red.v4)
__global__ void k_scatter2(const int* __restrict__ src, const int* __restrict__ dst,
                           float* __restrict__ out, int E) {
    long long tid = (long long)blockIdx.x * blockDim.x + threadIdx.x;
    if (tid >= (long long)E * 4) return;
    int e = (int)(tid >> 2), c = (int)(tid & 3);
    int s = __ldg(&src[e]);
    int d = __ldg(&dst[e]);
    float4 v = ((const float4*)(g_g2 + s * H2))[c];
    float* p = out + d * H2 + c * 4;
    asm volatile("red.global.add.v4.f32 [%0], {%1,%2,%3,%4};"
                 :: "l"(p), "f"(v.x), "f"(v.y), "f"(v.z), "f"(v.w) : "memory");
}

// vectorized: thread handles 4 consecutive outputs (quarter-row of H2=16)
__global__ void k_finish2(float* __restrict__ out, const float* __restrict__ b2, int nquads) {
    int i = blockIdx.x * blockDim.x + threadIdx.x;
    if (i < nquads) {
        int row = i >> 2;            // 4 quads per row of 16
        int q = (i & 3) * 4;
        float di = g_dinv[row];
        float4 b = *(const float4*)&b2[q];
        float4 v = *(float4*)&out[row * H2 + q];
        v.x = fmaf(di, v.x, b.x);
        v.y = fmaf(di, v.y, b.y);
        v.z = fmaf(di, v.z, b.z);
        v.w = fmaf(di, v.w, b.w);
        *(float4*)&out[row * H2 + q] = v;
    }
}

// ------------------------------------------------------------------ host ----
extern "C" void kernel_launch(void* const* d_in, const int* in_sizes, int n_in,
                              void* d_out, int out_size) {
    const float* x  = (const float*)d_in[0];
    const int*   ei = (const int*)d_in[1];
    const float* W1 = (const float*)d_in[2];
    const float* b1 = (const float*)d_in[3];
    const float* W2 = (const float*)d_in[4];
    const float* b2 = (const float*)d_in[5];
    float* out = (float*)d_out;

    int n = in_sizes[0] / F_IN;   // 100000
    int E = in_sizes[1] / 2;      // 3200000
    const int* src = ei;
    const int* dst = ei + E;

    k_zero_deg<<<(n + 255) / 256, 256>>>(n);
    k_count_deg<<<(E + 255) / 256, 256>>>(dst, E);
    k_gemm1<<<(n + 63) / 64, 256>>>(x, W1, n);
    k_scatter1<<<(int)(((long long)E * 8 + 255) / 256), 256>>>(src, dst, E);
    k_finish1_gemm2<<<(n + 7) / 8, 256>>>(W2, b1, out, n);
    k_scatter2<<<(int)(((long long)E * 4 + 255) / 256), 256>>>(src, dst, out, E);
    k_finish2<<<(n * 4 + 255) / 256, 256>>>(out, b2, n * 4);
}

// round 15
// speedup vs baseline: 1.0590x; 1.0590x over previous
#include <cuda_runtime.h>
#include <cuda_bf16.h>
#include <stdint.h>

// GCN 2-layer, atomic-scatter formulation:
//   g   = (x @ W) * dinv[row]           (dinv = rsqrt(indeg+1))
//   acc[d] = g[d] + sum_{e:dst=d} g[src_e]      (red.global.add.v4)
//   y   = dinv[d] * acc[d] + b

#define NMAX 100096
#define F_IN 128
#define H1 32
#define H2 16

__device__ float g_cnt[NMAX];         // edge in-degree (float), +1 folded later
__device__ float g_dinv[NMAX];
__device__ float g_g1[NMAX * H1];
__device__ float g_acc1[NMAX * H1];
__device__ float g_g2[NMAX * H2];

// ---------------------------------------------------------------- degree ----
__global__ void k_zero_deg(int n) {
    int i = blockIdx.x * blockDim.x + threadIdx.x;
    if (i < n) g_cnt[i] = 0.0f;
}

__global__ void k_count_deg(const int* __restrict__ dst, int E) {
    int e = blockIdx.x * blockDim.x + threadIdx.x;
    if (e < E) atomicAdd(&g_cnt[dst[e]], 1.0f);  // no-return -> RED
}

// ------------------------------------------------------------- layer 1 ------
// Register-tiled GEMM: thread = 8 contiguous rows x 4 cols (W crossbar
// amortized to 0.5 B/FMA); warp = 4 rowgroups x 8 colgroups -> 32 rows;
// block (8 warps) -> 256 rows. Single-buffered x loads (8 independent
// LDG.128 per k4), occupancy forced to 3 blocks/SM. Also computes dinv
// (self-loop +1 folded) and initializes acc1 = g1.
__global__ void __launch_bounds__(256, 3) k_gemm1(const float* __restrict__ x,
                                                  const float* __restrict__ W1, int n) {
    __shared__ float Ws[F_IN * H1];   // 16 KB
    int tid = threadIdx.x;
    for (int i = tid; i < F_IN * H1; i += 256) Ws[i] = W1[i];
    __syncthreads();

    int lane = tid & 31, warp = tid >> 5;
    int c0 = (lane & 7) * 4;          // colgroup -> 4 output cols
    int rg = lane >> 3;               // rowgroup (0..3)
    int rowbase = blockIdx.x * 256 + warp * 32 + rg * 8;

    const float* xb = x + (size_t)rowbase * F_IN;   // rows contiguous: +r*F_IN
    int nr = n - rowbase;             // rows valid: r < nr

    float acc[8][4] = {};
#pragma unroll
    for (int k4 = 0; k4 < F_IN; k4 += 4) {
        float4 xv[8];
#pragma unroll
        for (int r = 0; r < 8; r++) {
            xv[r] = (r < nr) ? __ldg((const float4*)(xb + r * F_IN + k4))
                             : make_float4(0.f, 0.f, 0.f, 0.f);
        }
        float4 w0 = *(const float4*)&Ws[(k4 + 0) * H1 + c0];
        float4 w1 = *(const float4*)&Ws[(k4 + 1) * H1 + c0];
        float4 w2 = *(const float4*)&Ws[(k4 + 2) * H1 + c0];
        float4 w3 = *(const float4*)&Ws[(k4 + 3) * H1 + c0];
#pragma unroll
        for (int r = 0; r < 8; r++) {
            acc[r][0] = fmaf(xv[r].x, w0.x, acc[r][0]);
            acc[r][1] = fmaf(xv[r].x, w0.y, acc[r][1]);
            acc[r][2] = fmaf(xv[r].x, w0.z, acc[r][2]);
            acc[r][3] = fmaf(xv[r].x, w0.w, acc[r][3]);
            acc[r][0] = fmaf(xv[r].y, w1.x, acc[r][0]);
            acc[r][1] = fmaf(xv[r].y, w1.y, acc[r][1]);
            acc[r][2] = fmaf(xv[r].y, w1.z, acc[r][2]);
            acc[r][3] = fmaf(xv[r].y, w1.w, acc[r][3]);
            acc[r][0] = fmaf(xv[r].z, w2.x, acc[r][0]);
            acc[r][1] = fmaf(xv[r].z, w2.y, acc[r][1]);
            acc[r][2] = fmaf(xv[r].z, w2.z, acc[r][2]);
            acc[r][3] = fmaf(xv[r].z, w2.w, acc[r][3]);
            acc[r][0] = fmaf(xv[r].w, w3.x, acc[r][0]);
            acc[r][1] = fmaf(xv[r].w, w3.y, acc[r][1]);
            acc[r][2] = fmaf(xv[r].w, w3.z, acc[r][2]);
            acc[r][3] = fmaf(xv[r].w, w3.w, acc[r][3]);
        }
    }

#pragma unroll
    for (int r = 0; r < 8; r++) {
        int row = rowbase + r;
        if (row < n) {
            float di = rsqrtf(g_cnt[row] + 1.0f);   // +1 = self loop
            if (c0 == 0) g_dinv[row] = di;  // one writer per row (colgroup 0)
            float4 v = make_float4(acc[r][0] * di, acc[r][1] * di,
                                   acc[r][2] * di, acc[r][3] * di);
            *(float4*)&g_g1[row * H1 + c0]   = v;
            *(float4*)&g_acc1[row * H1 + c0] = v;
        }
    }
}

// per-edge scatter: acc1[dst] += g1[src]  (32 floats = 8 x red.v4)
__global__ void k_scatter1(const int* __restrict__ src, const int* __restrict__ dst, int E) {
    long long tid = (long long)blockIdx.x * blockDim.x + threadIdx.x;
    if (tid >= (long long)E * 8) return;
    int e = (int)(tid >> 3), c = (int)(tid & 7);
    int s = __ldg(&src[e]);
    int d = __ldg(&dst[e]);
    float4 v = ((const float4*)(g_g1 + s * H1))[c];
    float* p = g_acc1 + d * H1 + c * 4;
    asm volatile("red.global.add.v4.f32 [%0], {%1,%2,%3,%4};"
                 :: "l"(p), "f"(v.x), "f"(v.y), "f"(v.z), "f"(v.w) : "memory");
}

// epilogue layer1 + GEMM2 fused (warp shuffles), writes g2 and out self-loop.
__global__ void k_finish1_gemm2(const float* __restrict__ W2, const float* __restrict__ b1,
                                float* __restrict__ out, int n) {
    __shared__ float W2s[H1 * H2];  // 2 KB
    __shared__ float b1s[H1];
    int tid = threadIdx.x;  // 256
    for (int i = tid; i < H1 * H2; i += 256) W2s[i] = W2[i];
    if (tid < H1) b1s[tid] = b1[tid];
    __syncthreads();

    int warp = tid >> 5, lane = tid & 31;
    int row = blockIdx.x * 8 + warp;
    if (row >= n) return;

    float di = g_dinv[row];
    float h = fmaxf(fmaf(di, g_acc1[row * H1 + lane], b1s[lane]), 0.0f);

    float acc = 0.0f;
    int j = lane & 15;
#pragma unroll
    for (int k = 0; k < H1; k++) {
        float v = __shfl_sync(0xffffffffu, h, k);
        acc = fmaf(v, W2s[k * H2 + j], acc);
    }
    if (lane < H2) {
        float g = acc * di;
        g_g2[row * H2 + lane] = g;
        out[row * H2 + lane]  = g;
    }
}

// per-edge scatter layer 2: out[dst] += g2[src]  (16 floats = 4 x red.v4)
__global__ void k_scatter2(const int* __restrict__ src, const int* __restrict__ dst,
                           float* __restrict__ out, int E) {
    long long tid = (long long)blockIdx.x * blockDim.x + threadIdx.x;
    if (tid >= (long long)E * 4) return;
    int e = (int)(tid >> 2), c = (int)(tid & 3);
    int s = __ldg(&src[e]);
    int d = __ldg(&dst[e]);
    float4 v = ((const float4*)(g_g2 + s * H2))[c];
    float* p = out + d * H2 + c * 4;
    asm volatile("red.global.add.v4.f32 [%0], {%1,%2,%3,%4};"
                 :: "l"(p), "f"(v.x), "f"(v.y), "f"(v.z), "f"(v.w) : "memory");
}

// vectorized: thread handles 4 consecutive outputs (quarter-row of H2=16)
__global__ void k_finish2(float* __restrict__ out, const float* __restrict__ b2, int nquads) {
    int i = blockIdx.x * blockDim.x + threadIdx.x;
    if (i < nquads) {
        int row = i >> 2;            // 4 quads per row of 16
        int q = (i & 3) * 4;
        float di = g_dinv[row];
        float4 b = *(const float4*)&b2[q];
        float4 v = *(float4*)&out[row * H2 + q];
        v.x = fmaf(di, v.x, b.x);
        v.y = fmaf(di, v.y, b.y);
        v.z = fmaf(di, v.z, b.z);
        v.w = fmaf(di, v.w, b.w);
        *(float4*)&out[row * H2 + q] = v;
    }
}

// ------------------------------------------------------------------ host ----
extern "C" void kernel_launch(void* const* d_in, const int* in_sizes, int n_in,
                              void* d_out, int out_size) {
    const float* x  = (const float*)d_in[0];
    const int*   ei = (const int*)d_in[1];
    const float* W1 = (const float*)d_in[2];
    const float* b1 = (const float*)d_in[3];
    const float* W2 = (const float*)d_in[4];
    const float* b2 = (const float*)d_in[5];
    float* out = (float*)d_out;

    int n = in_sizes[0] / F_IN;   // 100000
    int E = in_sizes[1] / 2;      // 3200000
    const int* src = ei;
    const int* dst = ei + E;

    k_zero_deg<<<(n + 255) / 256, 256>>>(n);
    k_count_deg<<<(E + 255) / 256, 256>>>(dst, E);
    k_gemm1<<<(n + 255) / 256, 256>>>(x, W1, n);
    k_scatter1<<<(int)(((long long)E * 8 + 255) / 256), 256>>>(src, dst, E);
    k_finish1_gemm2<<<(n + 7) / 8, 256>>>(W2, b1, out, n);
    k_scatter2<<<(int)(((long long)E * 4 + 255) / 256), 256>>>(src, dst, out, E);
    k_finish2<<<(n * 4 + 255) / 256, 256>>>(out, b2, n * 4);
}